// round 5
// baseline (speedup 1.0000x reference)
#include <cuda_runtime.h>
#include <cstdint>

#define SEQ   2048
#define EMB   1024
#define NH    16
#define HD    64
#define NTOK  8192      // B*S
#define NBH   64        // B*H

// Scratch
__device__ float g_Q[(size_t)NTOK * EMB];
__device__ float g_K[(size_t)NTOK * EMB];
__device__ float g_V[(size_t)NTOK * EMB];
__device__ float g_C[(size_t)NTOK * EMB];
__device__ float g_X[(size_t)NTOK * EMB];          // tf32-rounded x
__device__ float g_W[(size_t)4 * EMB * EMB];       // tf32-rounded Wq,Wk,Wv,Wo

__device__ __forceinline__ uint32_t f2t(float x) {
    uint32_t r; asm("cvt.rna.tf32.f32 %0, %1;" : "=r"(r) : "f"(x)); return r;
}
__device__ __forceinline__ float f2tf(float x) {
    return __uint_as_float(f2t(x));
}

__device__ __forceinline__ void mma8(float* d, const uint32_t* a, const uint32_t* b) {
    asm volatile(
        "mma.sync.aligned.m16n8k8.row.col.f32.tf32.tf32.f32 "
        "{%0,%1,%2,%3}, {%4,%5,%6,%7}, {%8,%9}, {%0,%1,%2,%3};\n"
        : "+f"(d[0]), "+f"(d[1]), "+f"(d[2]), "+f"(d[3])
        : "r"(a[0]), "r"(a[1]), "r"(a[2]), "r"(a[3]), "r"(b[0]), "r"(b[1]));
}

__device__ __forceinline__ uint32_t smem_u32(const void* p) {
    uint32_t a;
    asm("{ .reg .u64 t; cvta.to.shared.u64 t, %1; cvt.u32.u64 %0, t; }"
        : "=r"(a) : "l"(p));
    return a;
}
#define CP16(dst_u32, src_ptr) \
    asm volatile("cp.async.cg.shared.global [%0], [%1], 16;\n" \
                 :: "r"(dst_u32), "l"(src_ptr) : "memory")
#define CP_COMMIT() asm volatile("cp.async.commit_group;\n" ::: "memory")
#define CP_WAIT(n)  asm volatile("cp.async.wait_group %0;\n" :: "n"(n) : "memory")

// ===========================================================================
// Round x and W to tf32 (RNA) once; all later smem staging is raw copy.
// ===========================================================================
__global__ void round_inputs(
    const float4* __restrict__ x,
    const float4* __restrict__ wq, const float4* __restrict__ wk,
    const float4* __restrict__ wv, const float4* __restrict__ wo)
{
    const size_t NX = (size_t)NTOK * EMB / 4;
    const size_t NW = (size_t)EMB * EMB / 4;
    float4* X4 = (float4*)g_X;
    float4* W4 = (float4*)g_W;
    size_t stride = (size_t)gridDim.x * blockDim.x;
    for (size_t i = (size_t)blockIdx.x * blockDim.x + threadIdx.x;
         i < NX + 4 * NW; i += stride) {
        const float4* s; float4* d;
        if (i < NX) { s = x + i; d = X4 + i; }
        else {
            size_t j = i - NX;
            int w = (int)(j / NW);
            size_t o = j % NW;
            const float4* ws = (w == 0) ? wq : (w == 1) ? wk : (w == 2) ? wv : wo;
            s = ws + o; d = W4 + (size_t)w * NW + o;
        }
        float4 v = *s;
        float4 r;
        r.x = f2tf(v.x); r.y = f2tf(v.y); r.z = f2tf(v.z); r.w = f2tf(v.w);
        *d = r;
    }
}

// ===========================================================================
// TF32 GEMM via mma.sync: C[m,n] = sum_k A[m,k]*W[n,k] + bias[n]
// 128x128 CTA tile, BK=16, 256 thr, warps 2x4, warp tile 64x32.
// Row-major smem, stride 20 words (conflict-free frag loads: 20*g+t distinct).
// 4-slot cp.async pipeline, 3 stages in flight.
// ===========================================================================
#define GA_STR  20
#define GSTAGE_WORDS (2 * 128 * GA_STR)              // A + B = 5120 words
#define GEMM_SMEM_BYTES (4 * GSTAGE_WORDS * 4)       // 81920

__device__ __forceinline__ void gemm_prefetch(
    uint32_t smbase, int slot, const float* Arow, const float* Wrow,
    int cblk, int tid)
{
    const uint32_t sbase = smbase + slot * (GSTAGE_WORDS * 4);
#pragma unroll
    for (int p = 0; p < 4; p++) {
        const int ch  = tid + (p << 8);
        const int isB = ch >> 9;                 // 0: A, 1: B
        const int lc  = ch & 511;
        const int r   = lc & 127;
        const int c2  = lc >> 7;                 // 0..3
        const uint32_t dst = sbase + ((isB ? (128 * GA_STR) : 0)
                             + r * GA_STR + c2 * 4) * 4;
        const float* src = (isB ? Wrow : Arow)
                         + (size_t)r * EMB + cblk * 16 + c2 * 4;
        CP16(dst, src);
    }
    CP_COMMIT();
}

__device__ __forceinline__ void gemm_compute(
    const uint32_t* As, const uint32_t* Bs,
    int wm, int wn, int gid, int tq, float acc[4][4][4])
{
#pragma unroll
    for (int ks = 0; ks < 2; ks++) {
        const int kk = ks * 8;
        uint32_t af[4][4], bf[4][2];
#pragma unroll
        for (int mt = 0; mt < 4; mt++) {
            const int m0 = wm * 64 + mt * 16;
            af[mt][0] = As[(m0 + gid    ) * GA_STR + kk + tq];
            af[mt][1] = As[(m0 + gid + 8) * GA_STR + kk + tq];
            af[mt][2] = As[(m0 + gid    ) * GA_STR + kk + tq + 4];
            af[mt][3] = As[(m0 + gid + 8) * GA_STR + kk + tq + 4];
        }
#pragma unroll
        for (int nt = 0; nt < 4; nt++) {
            const int n0 = wn * 32 + nt * 8;
            bf[nt][0] = Bs[(n0 + gid) * GA_STR + kk + tq];
            bf[nt][1] = Bs[(n0 + gid) * GA_STR + kk + tq + 4];
        }
#pragma unroll
        for (int mt = 0; mt < 4; mt++)
#pragma unroll
            for (int nt = 0; nt < 4; nt++)
                mma8(acc[mt][nt], af[mt], bf[nt]);
    }
}

template<int TRANS_OUT>
__device__ __forceinline__ void gemm_body(
    const float* __restrict__ A, const float* __restrict__ W,
    const float* __restrict__ bias, float* __restrict__ Cout)
{
    extern __shared__ uint32_t smw[];
    const uint32_t smbase = smem_u32(smw);
    const int tid = threadIdx.x;
    const int warp = tid >> 5, lane = tid & 31;
    const int wm = warp >> 2, wn = warp & 3;
    const int gid = lane >> 2, tq = lane & 3;
    const int bm = blockIdx.y * 128, bn = blockIdx.x * 128;

    const float* Arow = A + (size_t)bm * EMB;
    const float* Wrow = W + (size_t)bn * EMB;

    float acc[4][4][4];
#pragma unroll
    for (int i = 0; i < 4; i++)
#pragma unroll
        for (int j = 0; j < 4; j++)
#pragma unroll
            for (int v = 0; v < 4; v++) acc[i][j][v] = 0.f;

    gemm_prefetch(smbase, 0, Arow, Wrow, 0, tid);
    gemm_prefetch(smbase, 1, Arow, Wrow, 1, tid);
    gemm_prefetch(smbase, 2, Arow, Wrow, 2, tid);

#pragma unroll 1
    for (int c = 0; c < EMB / 16; c++) {
        CP_WAIT(2);
        __syncthreads();
        const int nc = (c + 3 < EMB / 16) ? (c + 3) : (EMB / 16 - 1);
        gemm_prefetch(smbase, (c + 3) & 3, Arow, Wrow, nc, tid);
        const uint32_t* stg = smw + (size_t)(c & 3) * GSTAGE_WORDS;
        gemm_compute(stg, stg + 128 * GA_STR, wm, wn, gid, tq, acc);
    }

    // epilogue
#pragma unroll
    for (int mt = 0; mt < 4; mt++) {
#pragma unroll
        for (int nt = 0; nt < 4; nt++) {
            const int m_ = bm + wm * 64 + mt * 16 + gid;
            const int n_ = bn + wn * 32 + nt * 8 + 2 * tq;
            const float bz0 = bias[n_], bz1 = bias[n_ + 1];
            float c00 = acc[mt][nt][0] + bz0;
            float c01 = acc[mt][nt][1] + bz1;
            float c10 = acc[mt][nt][2] + bz0;
            float c11 = acc[mt][nt][3] + bz1;
            if (TRANS_OUT) {
                // Q/K/V are consumed by tf32 MMAs downstream: pre-round.
                c00 = f2tf(c00); c01 = f2tf(c01);
                c10 = f2tf(c10); c11 = f2tf(c11);
                const int b = m_ >> 11, s = m_ & (SEQ - 1);
                const int h = n_ >> 6,  d = n_ & 63;
                *(float2*)&Cout[((size_t)(b*NH+h)*SEQ + s) * HD + d]     = make_float2(c00, c01);
                *(float2*)&Cout[((size_t)(b*NH+h)*SEQ + s + 8) * HD + d] = make_float2(c10, c11);
            } else {
                *(float2*)&Cout[(size_t)m_ * EMB + n_]       = make_float2(c00, c01);
                *(float2*)&Cout[(size_t)(m_ + 8) * EMB + n_] = make_float2(c10, c11);
            }
        }
    }
}

__global__ void __launch_bounds__(256, 2) gemm_qkv(
    const float* __restrict__ A, const float* __restrict__ Wcat,
    const float* __restrict__ bq, const float* __restrict__ bk,
    const float* __restrict__ bv,
    float* __restrict__ Qo, float* __restrict__ Ko, float* __restrict__ Vo)
{
    const int z = blockIdx.z;
    const float* W = Wcat + (size_t)z * EMB * EMB;
    const float* b = (z == 0) ? bq : (z == 1) ? bk : bv;
    float* o = (z == 0) ? Qo : (z == 1) ? Ko : Vo;
    gemm_body<1>(A, W, b, o);
}

__global__ void __launch_bounds__(256, 2) gemm_o(
    const float* __restrict__ A, const float* __restrict__ W,
    const float* __restrict__ bias, float* __restrict__ out)
{
    gemm_body<0>(A, W, bias, out);
}

// ===========================================================================
// Fused attention, TF32 mma.sync, 512 threads.
// Row-major smem tiles (no transpose, no f2t on load — inputs pre-rounded):
//   Qs[128][68]  (A-op, stride≡4 mod 32)
//   Ks[2][128][68] (B-op of gemm1, frag addr g*68+t, double-buffered)
//   Vs[128][72]  (B-op of gemm2, frag addr t*72+g, single buffer)
//   Ps[128][132] (A-op of gemm2)
// cp.async prefetch of K/V one tile ahead.
// ===========================================================================
#define Q_STR  68
#define K_STR  68
#define V_STR  72
#define P_STR  132
#define QS_OFF 0
#define KS_OFF (128 * Q_STR)
#define VS_OFF (KS_OFF + 2 * 128 * K_STR)
#define PS_OFF (VS_OFF + 128 * V_STR)
#define ATTN_SMEM_WORDS (PS_OFF + 128 * P_STR)   // 52224 words = 208896 B

__device__ __forceinline__ void attn_cp_tile(
    uint32_t dst_base_u32, int stride_w, const float* src_base, int tid)
{
    // 128 rows x 64 words = 2048 x 16B chunks, 512 threads -> 4 each
#pragma unroll
    for (int p = 0; p < 4; p++) {
        const int ch = tid + (p << 9);
        const int r = ch >> 4;
        const int c = ch & 15;
        const uint32_t dst = dst_base_u32 + (r * stride_w + c * 4) * 4;
        const float* src = src_base + (size_t)r * HD + c * 4;
        CP16(dst, src);
    }
}

__global__ void __launch_bounds__(512, 1) attn_tf32(
    const float* __restrict__ Q, const float* __restrict__ K,
    const float* __restrict__ V, float* __restrict__ Cctx)
{
    extern __shared__ uint32_t sm[];
    const uint32_t smbase = smem_u32(sm);
    uint32_t* Qs = sm + QS_OFF;
    uint32_t* Vs = sm + VS_OFF;
    uint32_t* Ps = sm + PS_OFF;

    const int tid  = threadIdx.x;
    const int warp = tid >> 5, lane = tid & 31;
    const int gid  = lane >> 2, tq = lane & 3;
    const int wm1 = warp >> 2, wn1 = warp & 3;    // gemm1: 4x4, warp tile 32x32
    const int wm2 = warp >> 1, wn2 = warp & 1;    // gemm2: 8x2, warp tile 16x32
    const int bh = blockIdx.y;
    const int q0 = blockIdx.x * 128;

    const float* Qbh = Q + (size_t)bh * SEQ * HD;
    const float* Kbh = K + (size_t)bh * SEQ * HD;
    const float* Vbh = V + (size_t)bh * SEQ * HD;

    // prologue: group0 = Q + K0 ; group1 = V0
    attn_cp_tile(smbase + QS_OFF * 4, Q_STR, Qbh + (size_t)q0 * HD, tid);
    attn_cp_tile(smbase + KS_OFF * 4, K_STR, Kbh, tid);
    CP_COMMIT();
    attn_cp_tile(smbase + VS_OFF * 4, V_STR, Vbh, tid);
    CP_COMMIT();

    float acc2[4][4];
#pragma unroll
    for (int j = 0; j < 4; j++)
#pragma unroll
        for (int v = 0; v < 4; v++) acc2[j][v] = 0.f;

#pragma unroll 1
    for (int kt = 0; kt < 16; kt++) {
        // prefetch K(kt+1) into the other K buffer (clamped; redundant on last)
        const int nk = (kt + 1 < 16) ? (kt + 1) : 15;
        attn_cp_tile(smbase + (KS_OFF + ((kt + 1) & 1) * 128 * K_STR) * 4,
                     K_STR, Kbh + (size_t)nk * 128 * HD, tid);
        CP_COMMIT();
        CP_WAIT(2);                 // K(kt) (and everything before) arrived
        __syncthreads();            // S1: K visible to all

        const uint32_t* Ks = sm + KS_OFF + (kt & 1) * 128 * K_STR;

        // gemm1: S[i][j] = sum_d Q[i][d] K[j][d]
        float acc1[2][4][4];
#pragma unroll
        for (int i = 0; i < 2; i++)
#pragma unroll
            for (int j = 0; j < 4; j++)
#pragma unroll
                for (int v = 0; v < 4; v++) acc1[i][j][v] = 0.f;

#pragma unroll
        for (int ks = 0; ks < 8; ks++) {
            const int kk = ks * 8;
            uint32_t af[2][4], bf[4][2];
#pragma unroll
            for (int mt = 0; mt < 2; mt++) {
                const int m0 = wm1 * 32 + mt * 16;
                af[mt][0] = Qs[(m0 + gid    ) * Q_STR + kk + tq];
                af[mt][1] = Qs[(m0 + gid + 8) * Q_STR + kk + tq];
                af[mt][2] = Qs[(m0 + gid    ) * Q_STR + kk + tq + 4];
                af[mt][3] = Qs[(m0 + gid + 8) * Q_STR + kk + tq + 4];
            }
#pragma unroll
            for (int nt = 0; nt < 4; nt++) {
                const int n0 = wn1 * 32 + nt * 8;
                bf[nt][0] = Ks[(n0 + gid) * K_STR + kk + tq];
                bf[nt][1] = Ks[(n0 + gid) * K_STR + kk + tq + 4];
            }
#pragma unroll
            for (int mt = 0; mt < 2; mt++)
#pragma unroll
                for (int nt = 0; nt < 4; nt++)
                    mma8(acc1[mt][nt], af[mt], bf[nt]);
        }

        // softsign (1/sqrt(64) folded): p = s/(8+|s|) -> Ps[i][j] (tf32)
#pragma unroll
        for (int mt = 0; mt < 2; mt++) {
#pragma unroll
            for (int nt = 0; nt < 4; nt++) {
                const int row = wm1 * 32 + mt * 16 + gid;
                const int col = wn1 * 32 + nt * 8 + 2 * tq;
                float s0 = acc1[mt][nt][0], s1 = acc1[mt][nt][1];
                float s2 = acc1[mt][nt][2], s3 = acc1[mt][nt][3];
                uint2 p01 = make_uint2(f2t(__fdividef(s0, 8.f + fabsf(s0))),
                                       f2t(__fdividef(s1, 8.f + fabsf(s1))));
                uint2 p23 = make_uint2(f2t(__fdividef(s2, 8.f + fabsf(s2))),
                                       f2t(__fdividef(s3, 8.f + fabsf(s3))));
                *(uint2*)&Ps[(row    ) * P_STR + col] = p01;
                *(uint2*)&Ps[(row + 8) * P_STR + col] = p23;
            }
        }
        CP_WAIT(1);                 // V(kt) arrived
        __syncthreads();            // S2: P + V visible to all

        // gemm2: ctx[i][d] += sum_j P[i][j] V[j][d]
#pragma unroll
        for (int ks = 0; ks < 16; ks++) {
            const int kk = ks * 8;
            uint32_t af[4], bf[4][2];
            const int i0 = wm2 * 16;
            af[0] = Ps[(i0 + gid    ) * P_STR + kk + tq];
            af[1] = Ps[(i0 + gid + 8) * P_STR + kk + tq];
            af[2] = Ps[(i0 + gid    ) * P_STR + kk + tq + 4];
            af[3] = Ps[(i0 + gid + 8) * P_STR + kk + tq + 4];
#pragma unroll
            for (int nt = 0; nt < 4; nt++) {
                const int d0 = wn2 * 32 + nt * 8;
                bf[nt][0] = Vs[(kk + tq    ) * V_STR + d0 + gid];
                bf[nt][1] = Vs[(kk + tq + 4) * V_STR + d0 + gid];
            }
#pragma unroll
            for (int nt = 0; nt < 4; nt++)
                mma8(acc2[nt], af, bf[nt]);
        }
        __syncthreads();            // S3: all done reading Vs / Ps

        // prefetch V(kt+1) into the single V buffer (clamped)
        attn_cp_tile(smbase + VS_OFF * 4, V_STR,
                     Vbh + (size_t)nk * 128 * HD, tid);
        CP_COMMIT();
    }

    // epilogue: ctx -> [token, E], tf32-rounded for the raw-copy output GEMM
    const int b = bh >> 4, h = bh & 15;
#pragma unroll
    for (int nt = 0; nt < 4; nt++) {
        const int i = wm2 * 16 + gid;
        const int d = wn2 * 32 + nt * 8 + 2 * tq;
        float* base0 = &Cctx[(size_t)(b * SEQ + q0 + i    ) * EMB + h * HD + d];
        float* base1 = &Cctx[(size_t)(b * SEQ + q0 + i + 8) * EMB + h * HD + d];
        *(float2*)base0 = make_float2(f2tf(acc2[nt][0]), f2tf(acc2[nt][1]));
        *(float2*)base1 = make_float2(f2tf(acc2[nt][2]), f2tf(acc2[nt][3]));
    }
}

// ===========================================================================
extern "C" void kernel_launch(void* const* d_in, const int* in_sizes, int n_in,
                              void* d_out, int out_size)
{
    (void)in_sizes; (void)n_in; (void)out_size;
    const float* x  = (const float*)d_in[0];
    const float* Wq = (const float*)d_in[1];
    const float* bq = (const float*)d_in[2];
    const float* Wk = (const float*)d_in[3];
    const float* bk = (const float*)d_in[4];
    const float* Wv = (const float*)d_in[5];
    const float* bv = (const float*)d_in[6];
    const float* Wo = (const float*)d_in[7];
    const float* bo = (const float*)d_in[8];
    float* out = (float*)d_out;

    float *Qp, *Kp, *Vp, *Cp, *Xp, *Wp;
    cudaGetSymbolAddress((void**)&Qp, g_Q);
    cudaGetSymbolAddress((void**)&Kp, g_K);
    cudaGetSymbolAddress((void**)&Vp, g_V);
    cudaGetSymbolAddress((void**)&Cp, g_C);
    cudaGetSymbolAddress((void**)&Xp, g_X);
    cudaGetSymbolAddress((void**)&Wp, g_W);

    round_inputs<<<2048, 256>>>((const float4*)x, (const float4*)Wq,
                                (const float4*)Wk, (const float4*)Wv,
                                (const float4*)Wo);

    cudaFuncSetAttribute(gemm_qkv, cudaFuncAttributeMaxDynamicSharedMemorySize,
                         GEMM_SMEM_BYTES);
    cudaFuncSetAttribute(gemm_o, cudaFuncAttributeMaxDynamicSharedMemorySize,
                         GEMM_SMEM_BYTES);

    gemm_qkv<<<dim3(EMB / 128, NTOK / 128, 3), 256, GEMM_SMEM_BYTES>>>(
        Xp, Wp, bq, bk, bv, Qp, Kp, Vp);

    const size_t attn_smem = (size_t)ATTN_SMEM_WORDS * sizeof(uint32_t);
    cudaFuncSetAttribute(attn_tf32, cudaFuncAttributeMaxDynamicSharedMemorySize,
                         (int)attn_smem);
    attn_tf32<<<dim3(SEQ / 128, NBH), 512, attn_smem>>>(Qp, Kp, Vp, Cp);

    gemm_o<<<dim3(EMB / 128, NTOK / 128), 256, GEMM_SMEM_BYTES>>>(
        Cp, Wp + (size_t)3 * EMB * EMB, bo, out);
}

// round 6
// speedup vs baseline: 1.8299x; 1.8299x over previous
#include <cuda_runtime.h>
#include <cstdint>

#define SEQ   2048
#define EMB   1024
#define NH    16
#define HD    64
#define NTOK  8192      // B*S
#define NBH   64        // B*H

// Scratch
__device__ float g_Q[(size_t)NTOK * EMB];
__device__ float g_K[(size_t)NTOK * EMB];
__device__ float g_V[(size_t)NTOK * EMB];
__device__ float g_C[(size_t)NTOK * EMB];
__device__ float g_X[(size_t)NTOK * EMB];          // tf32-rounded x
__device__ float g_W[(size_t)4 * EMB * EMB];       // tf32-rounded Wq,Wk,Wv,Wo

__device__ __forceinline__ uint32_t f2t(float x) {
    uint32_t r; asm("cvt.rna.tf32.f32 %0, %1;" : "=r"(r) : "f"(x)); return r;
}
__device__ __forceinline__ float f2tf(float x) { return __uint_as_float(f2t(x)); }

__device__ __forceinline__ void mma8(float* d, const uint32_t* a, const uint32_t* b) {
    asm volatile(
        "mma.sync.aligned.m16n8k8.row.col.f32.tf32.tf32.f32 "
        "{%0,%1,%2,%3}, {%4,%5,%6,%7}, {%8,%9}, {%0,%1,%2,%3};\n"
        : "+f"(d[0]), "+f"(d[1]), "+f"(d[2]), "+f"(d[3])
        : "r"(a[0]), "r"(a[1]), "r"(a[2]), "r"(a[3]), "r"(b[0]), "r"(b[1]));
}

// ===========================================================================
// Round x and W to tf32 (RNA) once; all later smem staging is raw copy.
// ===========================================================================
__global__ void round_inputs(
    const float4* __restrict__ x,
    const float4* __restrict__ wq, const float4* __restrict__ wk,
    const float4* __restrict__ wv, const float4* __restrict__ wo)
{
    const size_t NX = (size_t)NTOK * EMB / 4;
    const size_t NW = (size_t)EMB * EMB / 4;
    float4* X4 = (float4*)g_X;
    float4* W4 = (float4*)g_W;
    size_t stride = (size_t)gridDim.x * blockDim.x;
    for (size_t i = (size_t)blockIdx.x * blockDim.x + threadIdx.x;
         i < NX + 4 * NW; i += stride) {
        const float4* s; float4* d;
        if (i < NX) { s = x + i; d = X4 + i; }
        else {
            size_t j = i - NX;
            int w = (int)(j / NW);
            size_t o = j % NW;
            const float4* ws = (w == 0) ? wq : (w == 1) ? wk : (w == 2) ? wv : wo;
            s = ws + o; d = W4 + (size_t)w * NW + o;
        }
        float4 v = *s;
        float4 r;
        r.x = f2tf(v.x); r.y = f2tf(v.y); r.z = f2tf(v.z); r.w = f2tf(v.w);
        *d = r;
    }
}

// ===========================================================================
// TF32 GEMM (mma.sync): C[m,n] = sum_k A[m,k]*W[n,k] + bias[n]
// 128x128 CTA tile, BK=16, 256 thr, warps 2x4, warp tile 64x32.
// Row-major smem stride 20 (frag loads conflict-free: (20g+t) mod 32 distinct).
// R3-proven pipeline: LDG next chunk -> compute current -> STS next -> sync.
// ===========================================================================
#define GA_STR 20

struct GemmSmem {
    uint32_t As[2][128 * GA_STR];
    uint32_t Bs[2][128 * GA_STR];
};

__device__ __forceinline__ void gemm_stage(
    uint32_t* As, uint32_t* Bs,
    const float4& a0, const float4& a1, const float4& w0, const float4& w1,
    int lrow, int lcol)
{
    *(float4*)&As[lrow * GA_STR + lcol]        = a0;
    *(float4*)&As[(lrow + 64) * GA_STR + lcol] = a1;
    *(float4*)&Bs[lrow * GA_STR + lcol]        = w0;
    *(float4*)&Bs[(lrow + 64) * GA_STR + lcol] = w1;
}

__device__ __forceinline__ void gemm_compute(
    const uint32_t* As, const uint32_t* Bs,
    int wm, int wn, int gid, int tq, float acc[4][4][4])
{
#pragma unroll
    for (int ks = 0; ks < 2; ks++) {
        const int kk = ks * 8;
        uint32_t af[4][4], bf[4][2];
#pragma unroll
        for (int mt = 0; mt < 4; mt++) {
            const int m0 = wm * 64 + mt * 16;
            af[mt][0] = As[(m0 + gid    ) * GA_STR + kk + tq];
            af[mt][1] = As[(m0 + gid + 8) * GA_STR + kk + tq];
            af[mt][2] = As[(m0 + gid    ) * GA_STR + kk + tq + 4];
            af[mt][3] = As[(m0 + gid + 8) * GA_STR + kk + tq + 4];
        }
#pragma unroll
        for (int nt = 0; nt < 4; nt++) {
            const int n0 = wn * 32 + nt * 8;
            bf[nt][0] = Bs[(n0 + gid) * GA_STR + kk + tq];
            bf[nt][1] = Bs[(n0 + gid) * GA_STR + kk + tq + 4];
        }
#pragma unroll
        for (int mt = 0; mt < 4; mt++)
#pragma unroll
            for (int nt = 0; nt < 4; nt++)
                mma8(acc[mt][nt], af[mt], bf[nt]);
    }
}

template<int TRANS_OUT>
__device__ __forceinline__ void gemm_body(
    const float* __restrict__ A, const float* __restrict__ W,
    const float* __restrict__ bias, float* __restrict__ Cout, GemmSmem& S)
{
    const int tid  = threadIdx.x;
    const int bm   = blockIdx.y * 128;
    const int bn   = blockIdx.x * 128;
    const int lrow = tid >> 2;
    const int lcol = (tid & 3) << 2;
    const int warp = tid >> 5, lane = tid & 31;
    const int wm = warp >> 2, wn = warp & 3;
    const int gid = lane >> 2, tq = lane & 3;

    const float* A0 = A + (size_t)(bm + lrow) * EMB + lcol;
    const float* A1 = A0 + (size_t)64 * EMB;
    const float* W0 = W + (size_t)(bn + lrow) * EMB + lcol;
    const float* W1 = W0 + (size_t)64 * EMB;

    float acc[4][4][4];
#pragma unroll
    for (int i = 0; i < 4; i++)
#pragma unroll
        for (int j = 0; j < 4; j++)
#pragma unroll
            for (int v = 0; v < 4; v++) acc[i][j][v] = 0.f;

    // prologue: stage chunk 0 into buffer 0
    float4 a0 = *(const float4*)(A0);
    float4 a1 = *(const float4*)(A1);
    float4 w0 = *(const float4*)(W0);
    float4 w1 = *(const float4*)(W1);
    gemm_stage(S.As[0], S.Bs[0], a0, a1, w0, w1, lrow, lcol);
    __syncthreads();

    int buf = 0;
#pragma unroll 1
    for (int k0 = 16; k0 < EMB; k0 += 16) {
        a0 = *(const float4*)(A0 + k0);
        a1 = *(const float4*)(A1 + k0);
        w0 = *(const float4*)(W0 + k0);
        w1 = *(const float4*)(W1 + k0);
        gemm_compute(S.As[buf], S.Bs[buf], wm, wn, gid, tq, acc);
        gemm_stage(S.As[buf ^ 1], S.Bs[buf ^ 1], a0, a1, w0, w1, lrow, lcol);
        __syncthreads();
        buf ^= 1;
    }
    gemm_compute(S.As[buf], S.Bs[buf], wm, wn, gid, tq, acc);

#pragma unroll
    for (int mt = 0; mt < 4; mt++) {
#pragma unroll
        for (int nt = 0; nt < 4; nt++) {
            const int m_ = bm + wm * 64 + mt * 16 + gid;
            const int n_ = bn + wn * 32 + nt * 8 + 2 * tq;
            const float bz0 = bias[n_], bz1 = bias[n_ + 1];
            float c00 = acc[mt][nt][0] + bz0;
            float c01 = acc[mt][nt][1] + bz1;
            float c10 = acc[mt][nt][2] + bz0;
            float c11 = acc[mt][nt][3] + bz1;
            if (TRANS_OUT) {
                // Q/K/V consumed by tf32 MMAs downstream: round once here.
                c00 = f2tf(c00); c01 = f2tf(c01);
                c10 = f2tf(c10); c11 = f2tf(c11);
                const int b = m_ >> 11, s = m_ & (SEQ - 1);
                const int h = n_ >> 6,  d = n_ & 63;
                *(float2*)&Cout[((size_t)(b*NH+h)*SEQ + s) * HD + d]     = make_float2(c00, c01);
                *(float2*)&Cout[((size_t)(b*NH+h)*SEQ + s + 8) * HD + d] = make_float2(c10, c11);
            } else {
                *(float2*)&Cout[(size_t)m_ * EMB + n_]       = make_float2(c00, c01);
                *(float2*)&Cout[(size_t)(m_ + 8) * EMB + n_] = make_float2(c10, c11);
            }
        }
    }
}

__global__ void __launch_bounds__(256, 2) gemm_qkv(
    const float* __restrict__ A, const float* __restrict__ Wcat,
    const float* __restrict__ bq, const float* __restrict__ bk,
    const float* __restrict__ bv,
    float* __restrict__ Qo, float* __restrict__ Ko, float* __restrict__ Vo)
{
    __shared__ GemmSmem S;
    const int z = blockIdx.z;
    const float* W = Wcat + (size_t)z * EMB * EMB;
    const float* b = (z == 0) ? bq : (z == 1) ? bk : bv;
    float* o = (z == 0) ? Qo : (z == 1) ? Ko : Vo;
    gemm_body<1>(A, W, b, o, S);
}

__global__ void __launch_bounds__(256, 2) gemm_o(
    const float* __restrict__ A, const float* __restrict__ W,
    const float* __restrict__ bias, float* __restrict__ out)
{
    __shared__ GemmSmem S;
    gemm_body<0>(A, W, bias, out, S);
}

// ===========================================================================
// Fused attention, TF32 mma.sync, 512 threads (16 warps).
// Row-major smem (layouts validated in R5), raw staging (inputs pre-rounded),
// register double-buffering of K (2 bufs) and V (1 buf, deferred STS).
//   Qs[128][68]   A-op of gemm1
//   Ks[2][128][68] B-op of gemm1
//   Vs[128][72]   B-op of gemm2 (k-major)
//   Ps[128][132]  A-op of gemm2
// ===========================================================================
#define Q_STR  68
#define K_STR  68
#define V_STR  72
#define P_STR  132
#define QS_OFF 0
#define KS_OFF (128 * Q_STR)
#define VS_OFF (KS_OFF + 2 * 128 * K_STR)
#define PS_OFF (VS_OFF + 128 * V_STR)
#define ATTN_SMEM_WORDS (PS_OFF + 128 * P_STR)   // 52224 words = 208896 B

__global__ void __launch_bounds__(512, 1) attn_tf32(
    const float* __restrict__ Q, const float* __restrict__ K,
    const float* __restrict__ V, float* __restrict__ Cctx)
{
    extern __shared__ uint32_t sm[];
    uint32_t* Qs = sm + QS_OFF;
    uint32_t* Vs = sm + VS_OFF;
    uint32_t* Ps = sm + PS_OFF;

    const int tid  = threadIdx.x;
    const int warp = tid >> 5, lane = tid & 31;
    const int gid  = lane >> 2, tq = lane & 3;
    const int wm1 = warp >> 2, wn1 = warp & 3;    // gemm1: 4x4, warp tile 32x32
    const int wm2 = warp >> 1, wn2 = warp & 1;    // gemm2: 8x2, warp tile 16x32
    const int bh = blockIdx.y;
    const int q0 = blockIdx.x * 128;

    const float* Qbh = Q + (size_t)bh * SEQ * HD;
    const float* Kbh = K + (size_t)bh * SEQ * HD;
    const float* Vbh = V + (size_t)bh * SEQ * HD;

    // per-thread staging coordinates: 4 chunks of 16B (r = row, c = col/4)
    int srow[4], scol[4];
#pragma unroll
    for (int p = 0; p < 4; p++) {
        const int idx = tid + (p << 9);
        srow[p] = idx >> 4;
        scol[p] = (idx & 15) << 2;
    }

    // prologue: Q tile, K0 -> buf0, V0
#pragma unroll
    for (int p = 0; p < 4; p++) {
        const float4 qv = *(const float4*)(Qbh + (size_t)(q0 + srow[p]) * HD + scol[p]);
        const float4 kv = *(const float4*)(Kbh + (size_t)srow[p] * HD + scol[p]);
        const float4 vv = *(const float4*)(Vbh + (size_t)srow[p] * HD + scol[p]);
        *(float4*)&Qs[srow[p] * Q_STR + scol[p]]            = qv;
        *(float4*)&sm[KS_OFF + srow[p] * K_STR + scol[p]]   = kv;
        *(float4*)&Vs[srow[p] * V_STR + scol[p]]            = vv;
    }
    __syncthreads();

    float acc2[4][4];
#pragma unroll
    for (int j = 0; j < 4; j++)
#pragma unroll
        for (int v = 0; v < 4; v++) acc2[j][v] = 0.f;

#pragma unroll 1
    for (int kt = 0; kt < 16; kt++) {
        const int nk = (kt + 1 < 16) ? (kt + 1) : 15;

        // issue loads for next tile (latency hidden under gemm1/gemm2)
        float4 kreg[4], vreg[4];
#pragma unroll
        for (int p = 0; p < 4; p++) {
            kreg[p] = *(const float4*)(Kbh + (size_t)(nk * 128 + srow[p]) * HD + scol[p]);
            vreg[p] = *(const float4*)(Vbh + (size_t)(nk * 128 + srow[p]) * HD + scol[p]);
        }

        const uint32_t* Ks = sm + KS_OFF + (kt & 1) * 128 * K_STR;

        // gemm1: S[i][j] = sum_d Q[i][d] K[j][d]
        float acc1[2][4][4];
#pragma unroll
        for (int i = 0; i < 2; i++)
#pragma unroll
            for (int j = 0; j < 4; j++)
#pragma unroll
                for (int v = 0; v < 4; v++) acc1[i][j][v] = 0.f;

#pragma unroll
        for (int ks = 0; ks < 8; ks++) {
            const int kk = ks * 8;
            uint32_t af[2][4], bf[4][2];
#pragma unroll
            for (int mt = 0; mt < 2; mt++) {
                const int m0 = wm1 * 32 + mt * 16;
                af[mt][0] = Qs[(m0 + gid    ) * Q_STR + kk + tq];
                af[mt][1] = Qs[(m0 + gid + 8) * Q_STR + kk + tq];
                af[mt][2] = Qs[(m0 + gid    ) * Q_STR + kk + tq + 4];
                af[mt][3] = Qs[(m0 + gid + 8) * Q_STR + kk + tq + 4];
            }
#pragma unroll
            for (int nt = 0; nt < 4; nt++) {
                const int n0 = wn1 * 32 + nt * 8;
                bf[nt][0] = Ks[(n0 + gid) * K_STR + kk + tq];
                bf[nt][1] = Ks[(n0 + gid) * K_STR + kk + tq + 4];
            }
#pragma unroll
            for (int mt = 0; mt < 2; mt++)
#pragma unroll
                for (int nt = 0; nt < 4; nt++)
                    mma8(acc1[mt][nt], af[mt], bf[nt]);
        }

        // STS K(kt+1) into the other buffer (not read by anyone now)
        {
            uint32_t* Kn = sm + KS_OFF + ((kt + 1) & 1) * 128 * K_STR;
#pragma unroll
            for (int p = 0; p < 4; p++)
                *(float4*)&Kn[srow[p] * K_STR + scol[p]] = kreg[p];
        }

        // softsign (1/sqrt(64) folded): p = s/(8+|s|) -> Ps[i][j] (tf32)
#pragma unroll
        for (int mt = 0; mt < 2; mt++) {
#pragma unroll
            for (int nt = 0; nt < 4; nt++) {
                const int row = wm1 * 32 + mt * 16 + gid;
                const int col = wn1 * 32 + nt * 8 + 2 * tq;
                float s0 = acc1[mt][nt][0], s1 = acc1[mt][nt][1];
                float s2 = acc1[mt][nt][2], s3 = acc1[mt][nt][3];
                uint2 p01 = make_uint2(f2t(__fdividef(s0, 8.f + fabsf(s0))),
                                       f2t(__fdividef(s1, 8.f + fabsf(s1))));
                uint2 p23 = make_uint2(f2t(__fdividef(s2, 8.f + fabsf(s2))),
                                       f2t(__fdividef(s3, 8.f + fabsf(s3))));
                *(uint2*)&Ps[(row    ) * P_STR + col] = p01;
                *(uint2*)&Ps[(row + 8) * P_STR + col] = p23;
            }
        }
        __syncthreads();   // syncA: P (and K next) visible; V still stable

        // gemm2: ctx[i][d] += sum_j P[i][j] V[j][d]
#pragma unroll
        for (int ks = 0; ks < 16; ks++) {
            const int kk = ks * 8;
            uint32_t af[4], bf[4][2];
            const int i0 = wm2 * 16;
            af[0] = Ps[(i0 + gid    ) * P_STR + kk + tq];
            af[1] = Ps[(i0 + gid + 8) * P_STR + kk + tq];
            af[2] = Ps[(i0 + gid    ) * P_STR + kk + tq + 4];
            af[3] = Ps[(i0 + gid + 8) * P_STR + kk + tq + 4];
#pragma unroll
            for (int nt = 0; nt < 4; nt++) {
                const int d0 = wn2 * 32 + nt * 8;
                bf[nt][0] = Vs[(kk + tq    ) * V_STR + d0 + gid];
                bf[nt][1] = Vs[(kk + tq + 4) * V_STR + d0 + gid];
            }
#pragma unroll
            for (int nt = 0; nt < 4; nt++)
                mma8(acc2[nt], af, bf[nt]);
        }
        __syncthreads();   // syncB: everyone done reading Vs / Ps

        // STS V(kt+1) into the single V buffer
#pragma unroll
        for (int p = 0; p < 4; p++)
            *(float4*)&Vs[srow[p] * V_STR + scol[p]] = vreg[p];
    }

    // epilogue: ctx -> [token, E], tf32-rounded for the raw-copy output GEMM
    const int b = bh >> 4, h = bh & 15;
#pragma unroll
    for (int nt = 0; nt < 4; nt++) {
        const int i = wm2 * 16 + gid;
        const int d = wn2 * 32 + nt * 8 + 2 * tq;
        float* base0 = &Cctx[(size_t)(b * SEQ + q0 + i    ) * EMB + h * HD + d];
        float* base1 = &Cctx[(size_t)(b * SEQ + q0 + i + 8) * EMB + h * HD + d];
        *(float2*)base0 = make_float2(f2tf(acc2[nt][0]), f2tf(acc2[nt][1]));
        *(float2*)base1 = make_float2(f2tf(acc2[nt][2]), f2tf(acc2[nt][3]));
    }
}

// ===========================================================================
extern "C" void kernel_launch(void* const* d_in, const int* in_sizes, int n_in,
                              void* d_out, int out_size)
{
    (void)in_sizes; (void)n_in; (void)out_size;
    const float* x  = (const float*)d_in[0];
    const float* Wq = (const float*)d_in[1];
    const float* bq = (const float*)d_in[2];
    const float* Wk = (const float*)d_in[3];
    const float* bk = (const float*)d_in[4];
    const float* Wv = (const float*)d_in[5];
    const float* bv = (const float*)d_in[6];
    const float* Wo = (const float*)d_in[7];
    const float* bo = (const float*)d_in[8];
    float* out = (float*)d_out;

    float *Qp, *Kp, *Vp, *Cp, *Xp, *Wp;
    cudaGetSymbolAddress((void**)&Qp, g_Q);
    cudaGetSymbolAddress((void**)&Kp, g_K);
    cudaGetSymbolAddress((void**)&Vp, g_V);
    cudaGetSymbolAddress((void**)&Cp, g_C);
    cudaGetSymbolAddress((void**)&Xp, g_X);
    cudaGetSymbolAddress((void**)&Wp, g_W);

    round_inputs<<<2048, 256>>>((const float4*)x, (const float4*)Wq,
                                (const float4*)Wk, (const float4*)Wv,
                                (const float4*)Wo);

    gemm_qkv<<<dim3(EMB / 128, NTOK / 128, 3), 256>>>(
        Xp, Wp, bq, bk, bv, Qp, Kp, Vp);

    const size_t attn_smem = (size_t)ATTN_SMEM_WORDS * sizeof(uint32_t);
    cudaFuncSetAttribute(attn_tf32, cudaFuncAttributeMaxDynamicSharedMemorySize,
                         (int)attn_smem);
    attn_tf32<<<dim3(SEQ / 128, NBH), 512, attn_smem>>>(Qp, Kp, Vp, Cp);

    gemm_o<<<dim3(EMB / 128, NTOK / 128), 256>>>(Cp, Wp + (size_t)3 * EMB * EMB, bo, out);
}